// round 8
// baseline (speedup 1.0000x reference)
#include <cuda_runtime.h>
#include <math.h>

// DIAGNOSTIC/CORRECTNESS-FIRST build: CTC forward, B=1024,T=1024,C=96,L=32,
// S=65, BLANK=95. Identical lattice & warp layout to prior rounds, but the
// whole recursion runs in DOUBLE precision with per-32-step exact mass
// normalization. Emissions use accurate expf (2-ulp). This splits the
// "structural vs numerical" hypothesis: double => error collapses iff the
// prior failures were numerical.

#define FULLMASK 0xffffffffu
#define Bn 1024
#define Tn 1024
#define Cn 96
#define Ln 32
#define BLANKC 95

static __device__ __forceinline__ double warp_sum32d(double v) {
    v += __shfl_xor_sync(FULLMASK, v, 16);
    v += __shfl_xor_sync(FULLMASK, v, 8);
    v += __shfl_xor_sync(FULLMASK, v, 4);
    v += __shfl_xor_sync(FULLMASK, v, 2);
    v += __shfl_xor_sync(FULLMASK, v, 1);
    return v;
}

// One time step. Lane l holds states s=l (L) and s=32+l (H); state 64 on
// lane 0 only. Emission probs p = exp(logit)/d with d the exact (double)
// softmax denominator; alpha updated in double.
#define STEPD(x0, x1, x2) do {                                                 \
    float h0 = expf(x0), h1 = expf(x1), h2 = expf(x2);                         \
    double d = warp_sum32d((double)h0 + (double)h1 + (double)h2);              \
    double rd = 1.0 / d;                                                       \
    float g0L = __shfl_sync(FULLMASK, h0, srcL);                               \
    float g1L = __shfl_sync(FULLMASK, h1, srcL);                               \
    float g2L = __shfl_sync(FULLMASK, h2, srcL);                               \
    float g0H = __shfl_sync(FULLMASK, h0, srcH);                               \
    float g1H = __shfl_sync(FULLMASK, h1, srcH);                               \
    float g2H = __shfl_sync(FULLMASK, h2, srcH);                               \
    float eBf = __shfl_sync(FULLMASK, h2, 31);       /* class 95 = blank */    \
    double eL = (double)((selL == 0) ? g0L : ((selL == 1) ? g1L : g2L)) * rd;  \
    double eH = (double)((selH == 0) ? g0H : ((selH == 1) ? g1H : g2H)) * rd;  \
    double eB = (double)eBf * rd;                                              \
    double s1L = __shfl_sync(FULLMASK, aL, idx1);  /* aL[lane-1], l0: aL[31]*/ \
    double s2L = __shfl_sync(FULLMASK, aL, idx2);  /* aL[lane-2], wrap */      \
    double s1H = __shfl_sync(FULLMASK, aH, idx1);                              \
    double s2H = __shfl_sync(FULLMASK, aH, idx2);                              \
    double pL = lane ? s1L : 0.0;                                              \
    double qL = skL ? s2L : 0.0;            /* skL false for lanes 0..2 */     \
    double pH = lane ? s1H : s1L;           /* state 32 prev = aL[31] */       \
    double qq = (lane < 2) ? s2L : s2H;     /* l0: aL[30], l1: aL[31] */       \
    double qH = skH ? qq : 0.0;                                                \
    double nL = (aL + pL + qL) * eL;                                           \
    double nH = (aH + pH + qH) * eH;                                           \
    if (lane == 0) a64 = (a64 + s1H) * eB;  /* s1H@l0 = aH[31] = state 63 */   \
    aL = nL; aH = nH;                                                          \
} while (0)

// Exact probability-mass renormalization: divide alpha by its total mass and
// accumulate log(mass). Invariant: lgacc + log(any alpha) is unchanged.
#define RENORMD do {                                                           \
    double mass = warp_sum32d(aL + aH + a64);   /* a64 nonzero on lane0 only */\
    lgacc += log(mass);                                                        \
    double inv = 1.0 / mass;                                                   \
    aL *= inv; aH *= inv; a64 *= inv;                                          \
} while (0)

// Prefetch 8 time steps (3 classes per lane each) into register arrays.
#define LOADG(t0, X0, X1, X2) {                                                \
    _Pragma("unroll")                                                          \
    for (int i = 0; i < 8; i++) {                                              \
        const float* r = xr + (size_t)((t0) + i) * Cn;                         \
        X0[i] = __ldcs(r);                                                     \
        X1[i] = __ldcs(r + 32);                                                \
        X2[i] = __ldcs(r + 64);                                                \
    }                                                                          \
}

__global__ void __launch_bounds__(128, 1)
ctc_fwd_kernel(const int* __restrict__ yti,    // y_true, dtype sniffed below
               const float* __restrict__ yp,   // y_pred [B,T,C]
               float* __restrict__ out) {      // [B,1]
    const int lane = threadIdx.x & 31;
    const int b = blockIdx.x * 4 + (threadIdx.x >> 5);
    const int idx1 = (lane + 31) & 31;
    const int idx2 = (lane + 30) & 31;

    // --- dtype sniff: int64 labels (values in [0,94]) have zero high words ---
    int w = (lane < 16) ? yti[2 * lane + 1] : 0;
    bool is64 = __all_sync(FULLMASK, w == 0);

    // --- per-thread extended-label classes and skip flags ---
    int extL = BLANKC, extH = BLANKC;
    bool skL = false, skH = false;
    if (lane & 1) {
        int k = (lane - 1) >> 1;        // label index for state s=lane
        int lk, lkm, l16, l15;
        if (is64) {
            const long long* p = (const long long*)yti + (long long)b * Ln;
            lk  = (int)p[k];
            lkm = (k >= 1) ? (int)p[k - 1] : -1;
            l16 = (int)p[k + 16];
            l15 = (int)p[k + 15];
        } else {
            const int* p = yti + b * Ln;
            lk  = p[k];
            lkm = (k >= 1) ? p[k - 1] : -1;
            l16 = p[k + 16];
            l15 = p[k + 15];
        }
        extL = lk;  extH = l16;
        skL = (k >= 1) && (lk != lkm);
        skH = (l16 != l15);
    }
    const int selL = extL >> 5, srcL = extL & 31;
    const int selH = extH >> 5, srcH = extH & 31;

    const float* xr = yp + (size_t)b * (Tn * Cn) + lane;

    // --- init via virtual pre-state: first STEPD (t=0) then yields
    //     alpha[0]=p(blank), alpha[1]=p(label0), rest 0 — matches reference ---
    double aL = (lane == 0) ? 1.0 : 0.0;
    double aH = 0.0, a64 = 0.0;
    double lgacc = 0.0;

    float A0[8], A1[8], A2[8], B0[8], B1[8], B2[8];
    LOADG(0, A0, A1, A2);
    LOADG(8, B0, B1, B2);

    for (int g = 0; g < Tn / 8; g += 2) {
        #pragma unroll
        for (int i = 0; i < 8; i++) STEPD(A0[i], A1[i], A2[i]);
        if (g + 2 < Tn / 8) LOADG((g + 2) * 8, A0, A1, A2);
        #pragma unroll
        for (int i = 0; i < 8; i++) STEPD(B0[i], B1[i], B2[i]);
        if (g + 3 < Tn / 8) LOADG((g + 3) * 8, B0, B1, B2);
        if ((g >> 1) & 1) RENORMD;   // every 32 steps; range safe in double
    }

    // loss = -( lgacc + log(alpha[63] + alpha[64]) )
    double a63 = __shfl_sync(FULLMASK, aH, 31);
    double endv = a63 + a64;                      // valid on lane 0
    double loss = -(lgacc + log(endv));
    if (lane == 0) out[b] = (float)loss;
}

extern "C" void kernel_launch(void* const* d_in, const int* in_sizes, int n_in,
                              void* d_out, int out_size) {
    // identify inputs by element count (y_true: 32768, y_pred: 100663296)
    const void* p0 = d_in[0];
    const void* p1 = d_in[1];
    const int*   yt;
    const float* yp;
    if (in_sizes[0] == Bn * Ln) {
        yt = (const int*)p0;   yp = (const float*)p1;
    } else {
        yt = (const int*)p1;   yp = (const float*)p0;
    }
    ctc_fwd_kernel<<<Bn / 4, 128>>>(yt, yp, (float*)d_out);
}

// round 16
// speedup vs baseline: 5.0178x; 5.0178x over previous
#include <cuda_runtime.h>

// CTC loss forward, B=1024, T=1024, C=96, L=32, S=65, BLANK=95.
// LOG-DOMAIN float recursion (the reference's own numeric regime — proven by
// the double build matching the reference to 8.6e-7) with deferred softmax
// normalization: alpha_raw[s] += raw logit each step; SLD = sum_t log-sum-exp
// of logits accumulated in double; loss = SLD - LSE2(alphaT[63], alphaT[64]).
// Per-state LSE3 via MUFU ex2/lg2. One warp per batch row, all state in
// registers, no shared memory, no barriers. -1e30 sentinels as in reference.

#define FULLMASK 0xffffffffu
#define Bn 1024
#define Tn 1024
#define Cn 96
#define Ln 32
#define BLANKC 95
#define NEGF -1e30f
#define LN2F 0.693147182f
#define L2EF 1.442695041f

static __device__ __forceinline__ float ex2f(float x) {
    float r; asm("ex2.approx.f32 %0, %1;" : "=f"(r) : "f"(x)); return r;
}
static __device__ __forceinline__ float lg2f(float x) {
    float r; asm("lg2.approx.f32 %0, %1;" : "=f"(r) : "f"(x)); return r;
}

static __device__ __forceinline__ float warp_sum32(float v) {
    v += __shfl_xor_sync(FULLMASK, v, 16);
    v += __shfl_xor_sync(FULLMASK, v, 8);
    v += __shfl_xor_sync(FULLMASK, v, 4);
    v += __shfl_xor_sync(FULLMASK, v, 2);
    v += __shfl_xor_sync(FULLMASK, v, 1);
    return v;
}

// One log-domain time step. Lane l holds states s=l (L) and s=32+l (H);
// state 64 is computed redundantly on all lanes from broadcast values.
#define STEP(x0, x1, x2) do {                                                  \
    /* softmax denominator: S = sum over 96 classes of e^x (no overflow:     */\
    /* |x|<~6 -> S < 96*e^6). ld = ln(S), accumulated in double.             */\
    float e0 = ex2f((x0) * L2EF), e1 = ex2f((x1) * L2EF), e2 = ex2f((x2) * L2EF);\
    float S  = warp_sum32(e0 + e1 + e2);                                       \
    sld += (double)(LN2F * lg2f(S));                                           \
    /* gather raw emission logits for this lane's two states + blank */        \
    float g0L = __shfl_sync(FULLMASK, x0, srcL);                               \
    float g1L = __shfl_sync(FULLMASK, x1, srcL);                               \
    float g2L = __shfl_sync(FULLMASK, x2, srcL);                               \
    float g0H = __shfl_sync(FULLMASK, x0, srcH);                               \
    float g1H = __shfl_sync(FULLMASK, x1, srcH);                               \
    float g2H = __shfl_sync(FULLMASK, x2, srcH);                               \
    float xB  = __shfl_sync(FULLMASK, x2, 31);  /* class 95 = blank */         \
    float xL  = (selL == 0) ? g0L : ((selL == 1) ? g1L : g2L);                 \
    float xH  = (selH == 0) ? g0H : ((selH == 1) ? g1H : g2H);                 \
    /* neighbor log-alphas */                                                  \
    float s1L = __shfl_sync(FULLMASK, aL, idx1);  /* aL[lane-1], l0: aL[31] */ \
    float s2L = __shfl_sync(FULLMASK, aL, idx2);  /* aL[lane-2], wrap */       \
    float s1H = __shfl_sync(FULLMASK, aH, idx1);                               \
    float s2H = __shfl_sync(FULLMASK, aH, idx2);                               \
    float b63 = __shfl_sync(FULLMASK, aH, 31);    /* state 63, all lanes */    \
    float pL  = lane ? s1L : NEGF;                                             \
    float qL  = skL ? s2L : NEGF;            /* skL false for lanes 0..2 */    \
    float pH  = lane ? s1H : s1L;            /* state 32 prev = state 31 */    \
    float qq  = (lane < 2) ? s2L : s2H;      /* l0: state 30, l1: state 31 */  \
    float qH  = skH ? qq : NEGF;                                               \
    /* LSE3 for state L */                                                     \
    float mL = fmaxf(fmaxf(aL, pL), qL);                                       \
    float uL = ex2f((aL - mL) * L2EF) + ex2f((pL - mL) * L2EF)                 \
             + ex2f((qL - mL) * L2EF);                                         \
    aL = fmaf(LN2F, lg2f(uL), mL) + xL;                                        \
    /* LSE3 for state H */                                                     \
    float mH = fmaxf(fmaxf(aH, pH), qH);                                       \
    float uH = ex2f((aH - mH) * L2EF) + ex2f((pH - mH) * L2EF)                 \
             + ex2f((qH - mH) * L2EF);                                         \
    aH = fmaf(LN2F, lg2f(uH), mH) + xH;                                        \
    /* LSE2 for state 64 (blank), replicated on all lanes */                   \
    float m6 = fmaxf(a64, b63);                                                \
    float u6 = ex2f((a64 - m6) * L2EF) + ex2f((b63 - m6) * L2EF);              \
    a64 = fmaf(LN2F, lg2f(u6), m6) + xB;                                       \
} while (0)

// Prefetch 8 time steps (3 classes per lane each) into register arrays.
#define LOADG(t0, X0, X1, X2) {                                                \
    _Pragma("unroll")                                                          \
    for (int i = 0; i < 8; i++) {                                              \
        const float* r = xr + (size_t)((t0) + i) * Cn;                         \
        X0[i] = __ldcs(r);                                                     \
        X1[i] = __ldcs(r + 32);                                                \
        X2[i] = __ldcs(r + 64);                                                \
    }                                                                          \
}

__global__ void __launch_bounds__(128, 1)
ctc_fwd_kernel(const int* __restrict__ yti,    // y_true, dtype sniffed below
               const float* __restrict__ yp,   // y_pred [B,T,C]
               float* __restrict__ out) {      // [B,1]
    const int lane = threadIdx.x & 31;
    const int b = blockIdx.x * 4 + (threadIdx.x >> 5);
    const int idx1 = (lane + 31) & 31;
    const int idx2 = (lane + 30) & 31;

    // --- dtype sniff: int64 labels (values in [0,94]) have zero high words ---
    int w = (lane < 16) ? yti[2 * lane + 1] : 0;
    bool is64 = __all_sync(FULLMASK, w == 0);

    // --- per-thread extended-label classes and skip flags ---
    int extL = BLANKC, extH = BLANKC;
    bool skL = false, skH = false;
    if (lane & 1) {
        int k = (lane - 1) >> 1;        // label index for state s=lane
        int lk, lkm, l16, l15;
        if (is64) {
            const long long* p = (const long long*)yti + (long long)b * Ln;
            lk  = (int)p[k];
            lkm = (k >= 1) ? (int)p[k - 1] : -1;
            l16 = (int)p[k + 16];
            l15 = (int)p[k + 15];
        } else {
            const int* p = yti + b * Ln;
            lk  = p[k];
            lkm = (k >= 1) ? p[k - 1] : -1;
            l16 = p[k + 16];
            l15 = p[k + 15];
        }
        extL = lk;  extH = l16;
        skL = (k >= 1) && (lk != lkm);
        skH = (l16 != l15);
    }
    const int selL = extL >> 5, srcL = extL & 31;
    const int selH = extH >> 5, srcH = extH & 31;

    const float* xr = yp + (size_t)b * (Tn * Cn) + lane;

    // --- log-domain init via virtual pre-state: after the t=0 STEP this gives
    //     alpha[0]=x(blank), alpha[1]=x(label0), rest -1e30 (SLD carries the
    //     log_softmax normalization) — exactly the reference's alpha0. ---
    float aL = (lane == 0) ? 0.f : NEGF;
    float aH = NEGF, a64 = NEGF;
    double sld = 0.0;

    float A0[8], A1[8], A2[8], B0[8], B1[8], B2[8];
    LOADG(0, A0, A1, A2);
    LOADG(8, B0, B1, B2);

    for (int g = 0; g < Tn / 8; g += 2) {
        #pragma unroll
        for (int i = 0; i < 8; i++) STEP(A0[i], A1[i], A2[i]);
        if (g + 2 < Tn / 8) LOADG((g + 2) * 8, A0, A1, A2);
        #pragma unroll
        for (int i = 0; i < 8; i++) STEP(B0[i], B1[i], B2[i]);
        if (g + 3 < Tn / 8) LOADG((g + 3) * 8, B0, B1, B2);
    }

    // loss = SLD - LSE2(alphaT[63], alphaT[64])
    float a63 = __shfl_sync(FULLMASK, aH, 31);
    float mE  = fmaxf(a63, a64);
    float uE  = ex2f((a63 - mE) * L2EF) + ex2f((a64 - mE) * L2EF);
    float lse = fmaf(LN2F, lg2f(uE), mE);
    float loss = (float)(sld - (double)lse);
    if (lane == 0) out[b] = loss;
}

extern "C" void kernel_launch(void* const* d_in, const int* in_sizes, int n_in,
                              void* d_out, int out_size) {
    // identify inputs by element count (y_true: 32768, y_pred: 100663296)
    const void* p0 = d_in[0];
    const void* p1 = d_in[1];
    const int*   yt;
    const float* yp;
    if (in_sizes[0] == Bn * Ln) {
        yt = (const int*)p0;   yp = (const float*)p1;
    } else {
        yt = (const int*)p1;   yp = (const float*)p0;
    }
    ctc_fwd_kernel<<<Bn / 4, 128>>>(yt, yp, (float*)d_out);
}

// round 17
// speedup vs baseline: 7.9545x; 1.5852x over previous
#include <cuda_runtime.h>

// CTC loss forward, B=1024, T=1024, C=96, L=32, S=65, BLANK=95.
// Two-kernel split (R16 profile: latency-bound, nothing saturated; the
// per-step softmax denominator + FP64 accumulate + gather shuffles were
// serialized into the recursion for no reason):
//   kernel 1: SLD partials — sum_t ln(sum_c exp x) over 64-step chunks,
//             fully parallel (16384 warps), DRAM-bound.
//   kernel 2: lean log-domain recursion — per step only 2 gathered LDG
//             (prefetched), 6 SHFL, 11 MUFU, zero FP64. LSE3 core identical
//             to the R16 kernel that passed at 8.6e-7.
// loss = SLD - LSE2(alphaT[63], alphaT[64]).

#define FULLMASK 0xffffffffu
#define Bn 1024
#define Tn 1024
#define Cn 96
#define Ln 32
#define BLANKC 95
#define NEGF -1e30f
#define LN2F 0.693147182f
#define L2EF 1.442695041f
#define NCHUNK 16
#define TCHUNK 64          // Tn / NCHUNK

__device__ double g_sld_part[Bn * NCHUNK];

static __device__ __forceinline__ float ex2f(float x) {
    float r; asm("ex2.approx.f32 %0, %1;" : "=f"(r) : "f"(x)); return r;
}
static __device__ __forceinline__ float lg2f(float x) {
    float r; asm("lg2.approx.f32 %0, %1;" : "=f"(r) : "f"(x)); return r;
}

static __device__ __forceinline__ float warp_sum32(float v) {
    v += __shfl_xor_sync(FULLMASK, v, 16);
    v += __shfl_xor_sync(FULLMASK, v, 8);
    v += __shfl_xor_sync(FULLMASK, v, 4);
    v += __shfl_xor_sync(FULLMASK, v, 2);
    v += __shfl_xor_sync(FULLMASK, v, 1);
    return v;
}

// ---------------- kernel 1: softmax-denominator partial sums ----------------
// One warp per (row, 64-t chunk). 16384 warps -> ~110 warps/SM, DRAM-bound.
__global__ void __launch_bounds__(128, 1)
sld_kernel(const float* __restrict__ yp) {
    const int lane = threadIdx.x & 31;
    const int wid  = blockIdx.x * 4 + (threadIdx.x >> 5);   // 0..16383
    const int b     = wid >> 4;
    const int chunk = wid & (NCHUNK - 1);
    const float* xr = yp + ((size_t)b * Tn + (size_t)chunk * TCHUNK) * Cn + lane;

    double acc0 = 0.0, acc1 = 0.0;          // 2 accumulators: break DADD chain
    for (int i = 0; i < TCHUNK; i += 2) {
        const float* r0 = xr + (size_t)i * Cn;
        const float* r1 = r0 + Cn;
        float a0 = __ldcs(r0), a1 = __ldcs(r0 + 32), a2 = __ldcs(r0 + 64);
        float c0 = __ldcs(r1), c1 = __ldcs(r1 + 32), c2 = __ldcs(r1 + 64);
        float sa = ex2f(a0 * L2EF) + ex2f(a1 * L2EF) + ex2f(a2 * L2EF);
        float sb = ex2f(c0 * L2EF) + ex2f(c1 * L2EF) + ex2f(c2 * L2EF);
        float Sa = warp_sum32(sa);
        float Sb = warp_sum32(sb);
        acc0 += (double)(LN2F * lg2f(Sa));
        acc1 += (double)(LN2F * lg2f(Sb));
    }
    if (lane == 0) g_sld_part[b * NCHUNK + chunk] = acc0 + acc1;
}

// ---------------- kernel 2: lean log-domain recursion ----------------
// Lane l holds states s=l (L) and s=32+l (H); state 64 replicated.
// Emissions come in via 2 gathered prefetched loads; blank via shfl from
// lane 0 (lane 0's L-state class is blank).
#define STEP(xl, xh) do {                                                      \
    float xB  = __shfl_sync(FULLMASK, xl, 0);      /* blank logit */           \
    float s1L = __shfl_sync(FULLMASK, aL, idx1);   /* aL[lane-1], l0: aL[31]*/ \
    float s2L = __shfl_sync(FULLMASK, aL, idx2);   /* aL[lane-2], wrap */      \
    float s1H = __shfl_sync(FULLMASK, aH, idx1);                               \
    float s2H = __shfl_sync(FULLMASK, aH, idx2);                               \
    float b63 = __shfl_sync(FULLMASK, aH, 31);     /* state 63 */              \
    float pL  = lane ? s1L : NEGF;                                             \
    float qL  = skL ? s2L : NEGF;             /* skL false for lanes 0..2 */   \
    float pH  = lane ? s1H : s1L;             /* state 32 prev = state 31 */   \
    float qq  = (lane < 2) ? s2L : s2H;       /* l0: st 30, l1: st 31 */       \
    float qH  = skH ? qq : NEGF;                                               \
    float mL = fmaxf(fmaxf(aL, pL), qL);                                       \
    float uL = ex2f((aL - mL) * L2EF) + ex2f((pL - mL) * L2EF)                 \
             + ex2f((qL - mL) * L2EF);                                         \
    aL = fmaf(LN2F, lg2f(uL), mL) + (xl);                                      \
    float mH = fmaxf(fmaxf(aH, pH), qH);                                       \
    float uH = ex2f((aH - mH) * L2EF) + ex2f((pH - mH) * L2EF)                 \
             + ex2f((qH - mH) * L2EF);                                         \
    aH = fmaf(LN2F, lg2f(uH), mH) + (xh);                                      \
    float m6 = fmaxf(a64, b63);                                                \
    float u6 = ex2f((a64 - m6) * L2EF) + ex2f((b63 - m6) * L2EF);              \
    a64 = fmaf(LN2F, lg2f(u6), m6) + xB;                                       \
} while (0)

// Prefetch 8 steps of the two per-lane emission logits.
#define LOADG2(t0, XL, XH) {                                                   \
    _Pragma("unroll")                                                          \
    for (int i = 0; i < 8; i++) {                                              \
        XL[i] = __ldcs(pLg + (size_t)((t0) + i) * Cn);                         \
        XH[i] = __ldcs(pHg + (size_t)((t0) + i) * Cn);                         \
    }                                                                          \
}

__global__ void __launch_bounds__(128, 1)
ctc_fwd_kernel(const int* __restrict__ yti,
               const float* __restrict__ yp,
               float* __restrict__ out) {
    const int lane = threadIdx.x & 31;
    const int b = blockIdx.x * 4 + (threadIdx.x >> 5);
    const int idx1 = (lane + 31) & 31;
    const int idx2 = (lane + 30) & 31;

    // dtype sniff: int64 labels (values in [0,94]) have zero high words
    int w = (lane < 16) ? yti[2 * lane + 1] : 0;
    bool is64 = __all_sync(FULLMASK, w == 0);

    // per-thread extended-label classes and skip flags
    int extL = BLANKC, extH = BLANKC;
    bool skL = false, skH = false;
    if (lane & 1) {
        int k = (lane - 1) >> 1;
        int lk, lkm, l16, l15;
        if (is64) {
            const long long* p = (const long long*)yti + (long long)b * Ln;
            lk  = (int)p[k];
            lkm = (k >= 1) ? (int)p[k - 1] : -1;
            l16 = (int)p[k + 16];
            l15 = (int)p[k + 15];
        } else {
            const int* p = yti + b * Ln;
            lk  = p[k];
            lkm = (k >= 1) ? p[k - 1] : -1;
            l16 = p[k + 16];
            l15 = p[k + 15];
        }
        extL = lk;  extH = l16;
        skL = (k >= 1) && (lk != lkm);
        skH = (l16 != l15);
    }

    const float* base = yp + (size_t)b * (Tn * Cn);
    const float* pLg = base + extL;     // gathered per-lane emission pointers
    const float* pHg = base + extH;

    // log-domain init via virtual pre-state (first STEP consumes t=0):
    float aL = (lane == 0) ? 0.f : NEGF;
    float aH = NEGF, a64 = NEGF;

    float AL[8], AH[8], BL[8], BH[8];
    LOADG2(0, AL, AH);
    LOADG2(8, BL, BH);

    for (int g = 0; g < Tn / 8; g += 2) {
        #pragma unroll
        for (int i = 0; i < 8; i++) STEP(AL[i], AH[i]);
        if (g + 2 < Tn / 8) LOADG2((g + 2) * 8, AL, AH);
        #pragma unroll
        for (int i = 0; i < 8; i++) STEP(BL[i], BH[i]);
        if (g + 3 < Tn / 8) LOADG2((g + 3) * 8, BL, BH);
    }

    // LSE of the two end states
    float a63 = __shfl_sync(FULLMASK, aH, 31);
    float mE  = fmaxf(a63, a64);
    float uE  = ex2f((a63 - mE) * L2EF) + ex2f((a64 - mE) * L2EF);
    float lse = fmaf(LN2F, lg2f(uE), mE);

    // deterministic tree-reduce of the 16 SLD partials
    double sld = (lane < NCHUNK) ? g_sld_part[b * NCHUNK + lane] : 0.0;
    sld += __shfl_xor_sync(FULLMASK, sld, 8);
    sld += __shfl_xor_sync(FULLMASK, sld, 4);
    sld += __shfl_xor_sync(FULLMASK, sld, 2);
    sld += __shfl_xor_sync(FULLMASK, sld, 1);

    float loss = (float)(sld - (double)lse);
    if (lane == 0) out[b] = loss;
}

extern "C" void kernel_launch(void* const* d_in, const int* in_sizes, int n_in,
                              void* d_out, int out_size) {
    const void* p0 = d_in[0];
    const void* p1 = d_in[1];
    const int*   yt;
    const float* yp;
    if (in_sizes[0] == Bn * Ln) {
        yt = (const int*)p0;   yp = (const float*)p1;
    } else {
        yt = (const int*)p1;   yp = (const float*)p0;
    }
    sld_kernel<<<Bn * NCHUNK / 4, 128>>>(yp);
    ctc_fwd_kernel<<<Bn / 4, 128>>>(yt, yp, (float*)d_out);
}